// round 1
// baseline (speedup 1.0000x reference)
#include <cuda_runtime.h>
#include <cstddef>

// Problem constants
#define K_CB   2048
#define D_DIM  512
#define B_DIM  16
#define N_DIM  8192
#define M_ROWS (B_DIM * N_DIM)   // 131072

// Tiling for the distance kernel
#define BM 128
#define BK 128
#define BD 16

// Scratch (no allocations allowed): codebook squared norms + int indices
__device__ float g_e2[K_CB];
__device__ int   g_ind[M_ROWS];

// ---------------------------------------------------------------------------
// Kernel 1: e2[k] = sum_d embed[k][d]^2
// ---------------------------------------------------------------------------
__global__ __launch_bounds__(128) void e2_kernel(const float* __restrict__ embed) {
    int k = blockIdx.x;
    const float* row = embed + (size_t)k * D_DIM;
    float s = 0.f;
    for (int d = threadIdx.x; d < D_DIM; d += 128) {
        float v = row[d];
        s += v * v;
    }
    #pragma unroll
    for (int o = 16; o > 0; o >>= 1) s += __shfl_down_sync(0xffffffffu, s, o);
    __shared__ float ws[4];
    if ((threadIdx.x & 31) == 0) ws[threadIdx.x >> 5] = s;
    __syncthreads();
    if (threadIdx.x == 0) g_e2[k] = ws[0] + ws[1] + ws[2] + ws[3];
}

// ---------------------------------------------------------------------------
// Kernel 2: fused scores + argmax.
//   Rows m = b*N + n (x stored [B, D, N] so a row tile = 128 consecutive n).
//   score[m,k] = 2 * dot(x_m, e_k) - e2[k];  track running argmax per row.
//   128x128 score tile per block, D tiled by 16, 256 threads, 8x8 micro-tile.
// ---------------------------------------------------------------------------
__global__ __launch_bounds__(256) void dist_kernel(const float* __restrict__ x,
                                                   const float* __restrict__ embed,
                                                   float* __restrict__ out_ind_f) {
    __shared__ float As[BD][BM];        // x tile, d-major
    __shared__ float Bs[BD][BK + 4];    // embed tile, d-major, padded
    __shared__ float sBest[BM][16];
    __shared__ int   sIdx[BM][16];

    const int m0 = blockIdx.x * BM;
    const int bb = m0 / N_DIM;
    const int n0 = m0 % N_DIM;
    const float* xbase = x + (size_t)bb * D_DIM * N_DIM + n0;

    const int tid = threadIdx.x;
    const int tr  = tid >> 4;   // 0..15 : row group (8 rows each)
    const int tc  = tid & 15;   // 0..15 : col group (8 cols each)

    float best[8];
    int   bidx[8];
    #pragma unroll
    for (int i = 0; i < 8; i++) { best[i] = -3.0e38f; bidx[i] = 0; }

    for (int kt = 0; kt < K_CB; kt += BK) {
        float acc[8][8];
        #pragma unroll
        for (int i = 0; i < 8; i++)
            #pragma unroll
            for (int j = 0; j < 8; j++) acc[i][j] = 0.f;

        for (int dt = 0; dt < D_DIM; dt += BD) {
            // Load x tile: 2048 elements, coalesced over n
            #pragma unroll
            for (int l = 0; l < 8; l++) {
                int i = tid + l * 256;
                int r = i & (BM - 1);
                int d = i >> 7;
                As[d][r] = xbase[(size_t)(dt + d) * N_DIM + r];
            }
            // Load embed tile: 2048 elements, 16-wide segments per codeword
            #pragma unroll
            for (int l = 0; l < 8; l++) {
                int i = tid + l * 256;
                int d = i & (BD - 1);
                int k = i >> 4;
                Bs[d][k] = embed[(size_t)(kt + k) * D_DIM + dt + d];
            }
            __syncthreads();

            #pragma unroll
            for (int dd = 0; dd < BD; dd++) {
                float4 a0 = *(const float4*)&As[dd][tr * 8];
                float4 a1 = *(const float4*)&As[dd][tr * 8 + 4];
                float4 b0 = *(const float4*)&Bs[dd][tc * 8];
                float4 b1 = *(const float4*)&Bs[dd][tc * 8 + 4];
                float a[8] = {a0.x, a0.y, a0.z, a0.w, a1.x, a1.y, a1.z, a1.w};
                float b[8] = {b0.x, b0.y, b0.z, b0.w, b1.x, b1.y, b1.z, b1.w};
                #pragma unroll
                for (int i = 0; i < 8; i++)
                    #pragma unroll
                    for (int j = 0; j < 8; j++)
                        acc[i][j] += a[i] * b[j];
            }
            __syncthreads();
        }

        // Fold this k-tile into the running argmax (ascending k + strict '>'
        // keeps the lowest index on ties, matching jnp.argmax).
        #pragma unroll
        for (int j = 0; j < 8; j++) {
            int k = kt + tc * 8 + j;
            float e2v = g_e2[k];
            #pragma unroll
            for (int i = 0; i < 8; i++) {
                float s = 2.0f * acc[i][j] - e2v;
                if (s > best[i]) { best[i] = s; bidx[i] = k; }
            }
        }
    }

    // Cross-thread (over tc) argmax reduce per row
    #pragma unroll
    for (int i = 0; i < 8; i++) {
        sBest[tr * 8 + i][tc] = best[i];
        sIdx [tr * 8 + i][tc] = bidx[i];
    }
    __syncthreads();
    if (tid < BM) {
        float bv = sBest[tid][0];
        int   bi = sIdx[tid][0];
        #pragma unroll
        for (int t = 1; t < 16; t++) {
            float v  = sBest[tid][t];
            int   vi = sIdx[tid][t];
            if (v > bv || (v == bv && vi < bi)) { bv = v; bi = vi; }
        }
        int m = m0 + tid;
        g_ind[m] = bi;
        out_ind_f[m] = (float)bi;
    }
}

// ---------------------------------------------------------------------------
// Kernel 3: quantize[b, d, n] = embed[ind[b,n], d] via transpose-through-smem.
// One block handles (b, 32 consecutive n) x full D.
// ---------------------------------------------------------------------------
__global__ __launch_bounds__(256) void gather_kernel(const float* __restrict__ embed,
                                                     float* __restrict__ out) {
    extern __shared__ float tile[];     // [32][513]
    __shared__ int inds[32];
    const int bb = blockIdx.y;
    const int n0 = blockIdx.x * 32;

    if (threadIdx.x < 32) inds[threadIdx.x] = g_ind[bb * N_DIM + n0 + threadIdx.x];
    __syncthreads();

    // Phase 1: load 32 codebook rows, coalesced over d
    for (int i = threadIdx.x; i < 32 * D_DIM; i += 256) {
        int n = i >> 9;          // /512
        int d = i & (D_DIM - 1);
        tile[n * 513 + d] = embed[(size_t)inds[n] * D_DIM + d];
    }
    __syncthreads();

    // Phase 2: write transposed, coalesced over n (128B per warp)
    float* obase = out + (size_t)bb * D_DIM * N_DIM + n0;
    for (int i = threadIdx.x; i < 32 * D_DIM; i += 256) {
        int n = i & 31;
        int d = i >> 5;
        obase[(size_t)d * N_DIM + n] = tile[n * 513 + d];
    }
}

// ---------------------------------------------------------------------------
extern "C" void kernel_launch(void* const* d_in, const int* in_sizes, int n_in,
                              void* d_out, int out_size) {
    const float* x     = (const float*)d_in[0];   // [B, D, N] f32
    const float* embed = (const float*)d_in[1];   // [K, D]    f32
    float* out   = (float*)d_out;
    float* out_q = out;                                   // [B, D, N]
    float* out_i = out + (size_t)B_DIM * D_DIM * N_DIM;   // [B, N] indices as f32

    (void)in_sizes; (void)n_in; (void)out_size;

    static const int gather_smem = 32 * 513 * (int)sizeof(float);  // 65664 B
    cudaFuncSetAttribute(gather_kernel, cudaFuncAttributeMaxDynamicSharedMemorySize,
                         gather_smem);

    e2_kernel<<<K_CB, 128>>>(embed);
    dist_kernel<<<M_ROWS / BM, 256>>>(x, embed, out_i);
    gather_kernel<<<dim3(N_DIM / 32, B_DIM), 256, gather_smem>>>(embed, out_q);
}